// round 17
// baseline (speedup 1.0000x reference)
#include <cuda_runtime.h>
#include <cuda_fp16.h>
#include <math.h>
#include <stdint.h>
#include <string.h>

// Problem constants
#define BB     16
#define JJ     256
#define KK     384
#define CMETA  6
#define CIN    8
#define WD     32
#define DEPTH  3
#define SS     32
#define JK     (JJ*KK)        // 98304
#define NPTS   (BB*JK)        // 1572864

// tensor k_main config
#define MT_TPB   128
#define MT_ROWS  128
#define MT_ITERS 4
#define MT_PTSBLK (MT_ROWS*MT_ITERS)   // 512
#define NMAINB  (NPTS/MT_PTSBLK)       // 3072

// front kernel
#define RPB   4
#define IMGB  (BB*(SS/RPB))      // 128 image blocks (4 rows each)
#define NTILE (RPB*(KK/32))      // 48 point-tiles per image block
#define CB    256
#define CPT   4
#define NCOMPB (NPTS/(CB*CPT))   // 1536

// k_main dynamic SMEM layout
#define WF4_N   (3*2*4*32)       // 768 uint4, [dkt][nt][lane]
#define WF0_N   (4*32)           // 128 uint2, [nt][lane]
#define XS_N    (4*32*9)
#define SMEM_BYTES (WF4_N*16 + WF0_N*8 + XS_N*4 + (BB*WD + DEPTH*WD + WD + 4)*4 + 2*128*4 + 256)

// Scratch (device globals; zero at module load; k_main's last block re-zeros)
__device__ float g_img_sum[BB][WD];
__device__ float g_img_cnt[BB];
__device__ int   g_nact;
__device__ int   g_done;
__device__ int   g_idx[NPTS];

__device__ __forceinline__ bool mask_at(const void* m, int fmt, int i) {
    if (fmt == 0) return ((const unsigned char*)m)[i] != 0;
    if (fmt == 1) return ((const int*)m)[i] != 0;
    return ((const float*)m)[i] != 0.0f;
}

__device__ __forceinline__ int detect_fmt_block(const void* mask) {
    unsigned int v = ((const unsigned int*)mask)[threadIdx.x & 255];
    int all_int = __syncthreads_and(v <= 1u);
    int all_flt = __syncthreads_and(v == 0u || v == 0x3F800000u);
    return all_int ? 1 : (all_flt ? 2 : 0);
}

__device__ __forceinline__ unsigned int rotl32(unsigned int x, int r) {
    return (x << r) | (x >> (32 - r));
}

// ---- fp16 split helpers ----
__device__ __forceinline__ uint32_t h2u(__half2 h) {
    uint32_t u; memcpy(&u, &h, 4); return u;
}
__device__ __forceinline__ void split_h2(float v0, float v1,
                                         uint32_t& hi2, uint32_t& lo2) {
    __half2 h = __floats2half2_rn(v0, v1);
    float e0 = __low2float(h);
    float e1 = __high2float(h);
    __half2 l = __floats2half2_rn(v0 - e0, v1 - e1);
    hi2 = h2u(h); lo2 = h2u(l);
}
__device__ __forceinline__ void mma_f16(float c[4],
                                        uint32_t a0, uint32_t a1, uint32_t a2, uint32_t a3,
                                        uint32_t b0, uint32_t b1) {
    asm("mma.sync.aligned.m16n8k16.row.col.f32.f16.f16.f32 "
        "{%0,%1,%2,%3},{%4,%5,%6,%7},{%8,%9},{%0,%1,%2,%3};"
        : "+f"(c[0]), "+f"(c[1]), "+f"(c[2]), "+f"(c[3])
        : "r"(a0), "r"(a1), "r"(a2), "r"(a3), "r"(b0), "r"(b1));
}

// ---------------------------------------------------------------------------
// Front kernel: blocks [0,IMGB) = tensor-core image branch with local gumbel
// selection (4 rows/block, 8 warps x 6 tiles); blocks [IMGB,..) = compaction.
// ---------------------------------------------------------------------------
__global__ void __launch_bounds__(256) k_front(
    const void* __restrict__ mask,
    const float* __restrict__ Imodel, const float* __restrict__ Iobs,
    const float* __restrict__ metadata,
    const float* __restrict__ W_img_in, const float* __restrict__ b_img_in,
    const float* __restrict__ W_img, const float* __restrict__ b_img,
    float* __restrict__ out)
{
    __shared__ unsigned int keys[JJ];
    __shared__ int selrows[RPB];
    __shared__ __align__(16) uint4 WF4i[WF4_N];
    __shared__ __align__(16) uint2 WF0i[WF0_N];
    __shared__ float bs0[WD];
    __shared__ float bsdi[DEPTH][WD];
    __shared__ __align__(16) float Xs[8][32][9];
    __shared__ float Mk[8][32];
    __shared__ int wsum[8];
    __shared__ int bbase;

    const int fmt = detect_fmt_block(mask);
    const int tid = threadIdx.x;

    if (blockIdx.x >= IMGB) {
        // ---------------- compaction role ----------------
        const int cb = blockIdx.x - IMGB;
        const int lane = tid & 31;
        const int wid = tid >> 5;
        const unsigned int lt = (1u << lane) - 1u;
        const int base = cb * CB * CPT;

        bool act[CPT];
        unsigned int bal[CPT];
        int wcnt = 0;
#pragma unroll
        for (int r = 0; r < CPT; r++) {
            const int p = base + r * CB + tid;
            act[r] = mask_at(mask, fmt, p);
            bal[r] = __ballot_sync(0xFFFFFFFFu, act[r]);
            wcnt += __popc(bal[r]);
            if (!act[r]) out[p] = 0.0f;
        }

        if (lane == 0) wsum[wid] = wcnt;
        __syncthreads();
        if (tid == 0) {
            int tot = 0;
#pragma unroll
            for (int w = 0; w < 8; w++) { int c = wsum[w]; wsum[w] = tot; tot += c; }
            bbase = atomicAdd(&g_nact, tot);
        }
        __syncthreads();

        int off = bbase + wsum[wid];
#pragma unroll
        for (int r = 0; r < CPT; r++) {
            if (act[r]) g_idx[off + __popc(bal[r] & lt)] = base + r * CB + tid;
            off += __popc(bal[r]);
        }
        return;
    }

    // ---------------- image role ----------------
    const int b = blockIdx.x / (SS / RPB);
    const int s0 = (blockIdx.x % (SS / RPB)) * RPB;

    {
        const int j = tid;
        const int rbase = (b * JJ + j) * KK;
        bool alive = false;
        for (int k = 0; k < KK; k++) {
            if (mask_at(mask, fmt, rbase + k)) { alive = true; break; }
        }

        const unsigned int n = (unsigned int)(b * JJ + j);
        unsigned int x0 = 0u;
        unsigned int x1 = n;
        const unsigned int ks0 = 0u;
        const unsigned int ks1 = 42u;
        const unsigned int ks2 = 0x1BD11BDAu ^ 42u;
        x0 += ks0; x1 += ks1;
#define TF_ROUND(r) { x0 += x1; x1 = rotl32(x1, (r)); x1 ^= x0; }
        TF_ROUND(13) TF_ROUND(15) TF_ROUND(26) TF_ROUND(6)
        x0 += ks1; x1 += ks2 + 1u;
        TF_ROUND(17) TF_ROUND(29) TF_ROUND(16) TF_ROUND(24)
        x0 += ks2; x1 += ks0 + 2u;
        TF_ROUND(13) TF_ROUND(15) TF_ROUND(26) TF_ROUND(6)
        x0 += ks0; x1 += ks1 + 3u;
        TF_ROUND(17) TF_ROUND(29) TF_ROUND(16) TF_ROUND(24)
        x0 += ks1; x1 += ks2 + 4u;
        TF_ROUND(13) TF_ROUND(15) TF_ROUND(26) TF_ROUND(6)
        x0 += ks2; x1 += ks0 + 5u;
#undef TF_ROUND
        const unsigned int bits = x0 ^ x1;
        const unsigned int keyv = alive ? ((bits >> 9) | 0x80000000u) : 0u;
        keys[j] = keyv;
        __syncthreads();

        int rank = 0;
        for (int t = 0; t < JJ; t++) {
            unsigned int s = keys[t];
            if (s > keyv || (s == keyv && t < j)) rank++;
        }
        if (rank >= s0 && rank < s0 + RPB) selrows[rank - s0] = j;
    }

    for (int t = tid; t < WF4_N; t += 256) {
        int lane = t & 31, nt = (t >> 5) & 3, dkt = t >> 7;
        int d = dkt >> 1, kt = dkt & 1;
        int n = (lane >> 2) + 8 * nt;
        int k0 = 2 * (lane & 3) + 16 * kt;
        uint32_t b0h, b0l, b1h, b1l;
        split_h2(W_img[(d * WD + k0) * WD + n],     W_img[(d * WD + k0 + 1) * WD + n], b0h, b0l);
        split_h2(W_img[(d * WD + k0 + 8) * WD + n], W_img[(d * WD + k0 + 9) * WD + n], b1h, b1l);
        WF4i[t] = make_uint4(b0h, b1h, b0l, b1l);
    }
    for (int t = tid; t < WF0_N; t += 256) {
        int lane = t & 31, nt = t >> 5;
        int n = (lane >> 2) + 8 * nt;
        int k0 = 2 * (lane & 3);
        uint32_t bh, bl;
        split_h2(W_img_in[k0 * WD + n], W_img_in[(k0 + 1) * WD + n], bh, bl);
        WF0i[t] = make_uint2(bh, bl);
    }
    for (int t = tid; t < WD; t += 256) bs0[t] = b_img_in[t];
    for (int t = tid; t < DEPTH * WD; t += 256) bsdi[t / WD][t % WD] = b_img[t];
    __syncthreads();

    const int w = tid >> 5;
    const int lane = tid & 31;
    const int g = lane >> 2;
    const int q = lane & 3;
    float* mXs = &Xs[w][0][0];
    float* mMk = &Mk[w][0];

    float colacc[8];
#pragma unroll
    for (int k = 0; k < 8; k++) colacc[k] = 0.0f;
    float cntacc = 0.0f;

#pragma unroll 1
    for (int t = w; t < NTILE; t += 8) {
        const int rr = t / (KK / 32);
        const int kk0 = (t % (KK / 32)) * 32;
        const int j = selrows[rr];
        const int p = (b * JJ + j) * KK + kk0 + lane;

        __syncwarp();
        {
            float* xr = mXs + lane * 9;
            xr[0] = Imodel[p];
            xr[1] = Iobs[p];
            const float* mp = metadata + (size_t)p * CMETA;
#pragma unroll
            for (int i = 0; i < CMETA; i++) xr[2 + i] = mp[i];
            mMk[lane] = mask_at(mask, fmt, p) ? 1.0f : 0.0f;
        }
        __syncwarp();
        cntacc += mMk[lane];

        float cc[2][4][4];
#pragma unroll
        for (int mt = 0; mt < 2; mt++)
#pragma unroll
            for (int nt = 0; nt < 4; nt++)
#pragma unroll
                for (int r = 0; r < 4; r++) cc[mt][nt][r] = 0.0f;

        uint32_t aH[2][2][4], aL[2][2][4];
        {
            uint32_t iH[2][2], iL[2][2];
#pragma unroll
            for (int mt = 0; mt < 2; mt++) {
                const int R = 16 * mt;
                split_h2(mXs[(R + g) * 9 + 2 * q],     mXs[(R + g) * 9 + 2 * q + 1],
                         iH[mt][0], iL[mt][0]);
                split_h2(mXs[(R + g + 8) * 9 + 2 * q], mXs[(R + g + 8) * 9 + 2 * q + 1],
                         iH[mt][1], iL[mt][1]);
            }
#pragma unroll
            for (int nt = 0; nt < 4; nt++) {
                uint2 wv = WF0i[nt * 32 + lane];
#pragma unroll
                for (int mt = 0; mt < 2; mt++) {
                    mma_f16(cc[mt][nt], iH[mt][0], iH[mt][1], 0u, 0u, wv.x, 0u);
                    mma_f16(cc[mt][nt], iL[mt][0], iL[mt][1], 0u, 0u, wv.x, 0u);
                    mma_f16(cc[mt][nt], iH[mt][0], iH[mt][1], 0u, 0u, wv.y, 0u);
                }
            }
        }

#pragma unroll
        for (int mt = 0; mt < 2; mt++)
#pragma unroll
            for (int nt = 0; nt < 4; nt++) {
                const int kt = nt >> 1;
                const int ai = (nt & 1) * 2;
                const int c0 = 8 * nt + 2 * q;
                split_h2(cc[mt][nt][0] + bs0[c0], cc[mt][nt][1] + bs0[c0 + 1],
                         aH[mt][kt][ai], aL[mt][kt][ai]);
                split_h2(cc[mt][nt][2] + bs0[c0], cc[mt][nt][3] + bs0[c0 + 1],
                         aH[mt][kt][ai + 1], aL[mt][kt][ai + 1]);
            }

#pragma unroll
        for (int d = 0; d < DEPTH; d++) {
#pragma unroll
            for (int mt = 0; mt < 2; mt++)
#pragma unroll
                for (int nt = 0; nt < 4; nt++)
#pragma unroll
                    for (int r = 0; r < 4; r++) cc[mt][nt][r] = 0.0f;

#pragma unroll
            for (int kt = 0; kt < 2; kt++) {
#pragma unroll
                for (int nt = 0; nt < 4; nt++) {
                    uint4 wv = WF4i[((d * 2 + kt) * 4 + nt) * 32 + lane];
#pragma unroll
                    for (int mt = 0; mt < 2; mt++) {
                        mma_f16(cc[mt][nt], aH[mt][kt][0], aH[mt][kt][1], aH[mt][kt][2], aH[mt][kt][3], wv.x, wv.y);
                        mma_f16(cc[mt][nt], aL[mt][kt][0], aL[mt][kt][1], aL[mt][kt][2], aL[mt][kt][3], wv.x, wv.y);
                        mma_f16(cc[mt][nt], aH[mt][kt][0], aH[mt][kt][1], aH[mt][kt][2], aH[mt][kt][3], wv.z, wv.w);
                    }
                }
            }

            if (d < DEPTH - 1) {
#pragma unroll
                for (int mt = 0; mt < 2; mt++)
#pragma unroll
                    for (int nt = 0; nt < 4; nt++) {
                        const int kt = nt >> 1;
                        const int ai = (nt & 1) * 2;
                        const int c0 = 8 * nt + 2 * q;
                        const float bb0 = bsdi[d][c0];
                        const float bb1 = bsdi[d][c0 + 1];
                        split_h2(fmaxf(cc[mt][nt][0] + bb0, 0.0f),
                                 fmaxf(cc[mt][nt][1] + bb1, 0.0f),
                                 aH[mt][kt][ai], aL[mt][kt][ai]);
                        split_h2(fmaxf(cc[mt][nt][2] + bb0, 0.0f),
                                 fmaxf(cc[mt][nt][3] + bb1, 0.0f),
                                 aH[mt][kt][ai + 1], aL[mt][kt][ai + 1]);
                    }
            } else {
#pragma unroll
                for (int mt = 0; mt < 2; mt++) {
                    const float m0 = mMk[16 * mt + g];
                    const float m1 = mMk[16 * mt + g + 8];
#pragma unroll
                    for (int nt = 0; nt < 4; nt++) {
                        const int c0 = 8 * nt + 2 * q;
                        const float bb0 = bsdi[d][c0];
                        const float bb1 = bsdi[d][c0 + 1];
                        float v0 = fmaxf(cc[mt][nt][0] + bb0, 0.0f);
                        float v1 = fmaxf(cc[mt][nt][1] + bb1, 0.0f);
                        float v2 = fmaxf(cc[mt][nt][2] + bb0, 0.0f);
                        float v3 = fmaxf(cc[mt][nt][3] + bb1, 0.0f);
                        colacc[nt * 2 + 0] += m0 * v0 + m1 * v2;
                        colacc[nt * 2 + 1] += m0 * v1 + m1 * v3;
                    }
                }
            }
        }
    }

#pragma unroll
    for (int k = 0; k < 8; k++) {
        colacc[k] += __shfl_xor_sync(0xFFFFFFFFu, colacc[k], 4);
        colacc[k] += __shfl_xor_sync(0xFFFFFFFFu, colacc[k], 8);
        colacc[k] += __shfl_xor_sync(0xFFFFFFFFu, colacc[k], 16);
    }
    if (lane < 4) {
#pragma unroll
        for (int nt = 0; nt < 4; nt++) {
            atomicAdd(&g_img_sum[b][8 * nt + 2 * lane + 0], colacc[nt * 2 + 0]);
            atomicAdd(&g_img_sum[b][8 * nt + 2 * lane + 1], colacc[nt * 2 + 1]);
        }
    }
#pragma unroll
    for (int o = 16; o > 0; o >>= 1) cntacc += __shfl_xor_sync(0xFFFFFFFFu, cntacc, o);
    if (lane == 0) atomicAdd(&g_img_cnt[b], cntacc);
}

// ---------------------------------------------------------------------------
// Kernel 2: fp16 Markidis tensor k_main; 16-row halves processed sequentially
// to halve fragment registers -> 5 blocks/SM (20 warps).
// ---------------------------------------------------------------------------
__global__ void __launch_bounds__(MT_TPB, 5) k_main(
    const float* __restrict__ metadata,
    const float* __restrict__ W_lin_in, const float* __restrict__ b_lin_in,
    const float* __restrict__ W_mlp, const float* __restrict__ b_mlp,
    const float* __restrict__ W_out, const float* __restrict__ b_out,
    float* __restrict__ out)
{
    extern __shared__ __align__(16) unsigned char dynsmem[];
    uint4* WF4   = (uint4*)dynsmem;
    uint2* WF0   = (uint2*)(WF4 + WF4_N);
    float* Xs    = (float*)(WF0 + WF0_N);
    float* beffs = Xs + XS_N;
    float* bsd   = beffs + BB * WD;
    float* wout_s= bsd + DEPTH * WD;
    float* bout_s= wout_s + WD;
    int*   xb    = (int*)(bout_s + 4);
    int*   xp    = xb + 128;

    const int tid = threadIdx.x;

    for (int t = tid; t < WF4_N; t += MT_TPB) {
        int lane = t & 31, nt = (t >> 5) & 3, dkt = t >> 7;
        int d = dkt >> 1, kt = dkt & 1;
        int n = (lane >> 2) + 8 * nt;
        int k0 = 2 * (lane & 3) + 16 * kt;
        uint32_t b0h, b0l, b1h, b1l;
        split_h2(W_mlp[(d * WD + k0) * WD + n],     W_mlp[(d * WD + k0 + 1) * WD + n], b0h, b0l);
        split_h2(W_mlp[(d * WD + k0 + 8) * WD + n], W_mlp[(d * WD + k0 + 9) * WD + n], b1h, b1l);
        WF4[t] = make_uint4(b0h, b1h, b0l, b1l);
    }
    for (int t = tid; t < WF0_N; t += MT_TPB) {
        int lane = t & 31, nt = t >> 5;
        int n = (lane >> 2) + 8 * nt;
        int k0 = 2 * (lane & 3);
        float w0 = (k0 < CMETA) ? W_lin_in[k0 * WD + n] : 0.0f;
        float w1 = (k0 + 1 < CMETA) ? W_lin_in[(k0 + 1) * WD + n] : 0.0f;
        uint32_t bh, bl;
        split_h2(w0, w1, bh, bl);
        WF0[t] = make_uint2(bh, bl);
    }
    for (int t = tid; t < BB * WD; t += MT_TPB) {
        int bb = t / WD, c = t % WD;
        beffs[t] = b_lin_in[c] + g_img_sum[bb][c] / g_img_cnt[bb];
    }
    for (int t = tid; t < DEPTH * WD; t += MT_TPB) bsd[t] = b_mlp[t];
    if (tid < WD) wout_s[tid] = W_out[tid];
    if (tid == 0) bout_s[0] = b_out[0];
    __syncthreads();

    const int n_act = g_nact;
    const int w = tid >> 5;
    const int lane = tid & 31;
    const int g = lane >> 2;
    const int q = lane & 3;
    const int blkbase = blockIdx.x * MT_PTSBLK;

    float wo[8];
#pragma unroll
    for (int nt = 0; nt < 4; nt++) {
        wo[nt * 2 + 0] = wout_s[8 * nt + 2 * q + 0];
        wo[nt * 2 + 1] = wout_s[8 * nt + 2 * q + 1];
    }
    const float boutv = bout_s[0];
    float* mXs = Xs + w * 32 * 9;
    int* myxb = xb + w * 32;
    int* myxp = xp + w * 32;

    if (blkbase < n_act) {
#pragma unroll 1
        for (int it = 0; it < MT_ITERS; it++) {
            if (blkbase + it * MT_ROWS >= n_act) break;
            const int slot = blkbase + it * MT_ROWS + tid;
            const bool valid = slot < n_act;
            const int p = valid ? g_idx[slot] : 0;

            __syncwarp();
            {
                const float* mp = metadata + (size_t)p * CMETA;
                float* xr = mXs + lane * 9;
#pragma unroll
                for (int i = 0; i < CMETA; i++) xr[i] = mp[i];
                xr[6] = 0.0f; xr[7] = 0.0f;
                myxb[lane] = p / JK;
                myxp[lane] = valid ? p : -1;
            }
            __syncwarp();

            // ---- two 16-row halves, processed sequentially ----
#pragma unroll 1
            for (int mh = 0; mh < 2; mh++) {
                const int R = 16 * mh;
                const int b2[2] = { myxb[R + g], myxb[R + g + 8] };

                float cc[4][4];
#pragma unroll
                for (int nt = 0; nt < 4; nt++)
#pragma unroll
                    for (int r = 0; r < 4; r++) cc[nt][r] = 0.0f;

                uint32_t aH[2][4], aL[2][4];
                {
                    uint32_t iH[2], iL[2];
                    split_h2(mXs[(R + g) * 9 + 2 * q],     mXs[(R + g) * 9 + 2 * q + 1],
                             iH[0], iL[0]);
                    split_h2(mXs[(R + g + 8) * 9 + 2 * q], mXs[(R + g + 8) * 9 + 2 * q + 1],
                             iH[1], iL[1]);
#pragma unroll
                    for (int nt = 0; nt < 4; nt++) {
                        uint2 wv = WF0[nt * 32 + lane];
                        mma_f16(cc[nt], iH[0], iH[1], 0u, 0u, wv.x, 0u);
                        mma_f16(cc[nt], iL[0], iL[1], 0u, 0u, wv.x, 0u);
                        mma_f16(cc[nt], iH[0], iH[1], 0u, 0u, wv.y, 0u);
                    }
                }

                // input epilogue: + per-batch bias -> A frags
#pragma unroll
                for (int nt = 0; nt < 4; nt++) {
                    const int kt = nt >> 1;
                    const int ai = (nt & 1) * 2;
                    const int c0 = 8 * nt + 2 * q;
                    const float* be0 = &beffs[b2[0] * WD];
                    const float* be1 = &beffs[b2[1] * WD];
                    split_h2(cc[nt][0] + be0[c0], cc[nt][1] + be0[c0 + 1],
                             aH[kt][ai], aL[kt][ai]);
                    split_h2(cc[nt][2] + be1[c0], cc[nt][3] + be1[c0 + 1],
                             aH[kt][ai + 1], aL[kt][ai + 1]);
                }

                float acc2[2] = {0.0f, 0.0f};
#pragma unroll
                for (int d = 0; d < DEPTH; d++) {
#pragma unroll
                    for (int nt = 0; nt < 4; nt++)
#pragma unroll
                        for (int r = 0; r < 4; r++) cc[nt][r] = 0.0f;

#pragma unroll
                    for (int kt = 0; kt < 2; kt++) {
#pragma unroll
                        for (int nt = 0; nt < 4; nt++) {
                            uint4 wv = WF4[((d * 2 + kt) * 4 + nt) * 32 + lane];
                            mma_f16(cc[nt], aH[kt][0], aH[kt][1], aH[kt][2], aH[kt][3], wv.x, wv.y);
                            mma_f16(cc[nt], aL[kt][0], aL[kt][1], aL[kt][2], aL[kt][3], wv.x, wv.y);
                            mma_f16(cc[nt], aH[kt][0], aH[kt][1], aH[kt][2], aH[kt][3], wv.z, wv.w);
                        }
                    }

                    if (d < DEPTH - 1) {
#pragma unroll
                        for (int nt = 0; nt < 4; nt++) {
                            const int kt = nt >> 1;
                            const int ai = (nt & 1) * 2;
                            const int c0 = 8 * nt + 2 * q;
                            const float bb0 = bsd[d * WD + c0];
                            const float bb1 = bsd[d * WD + c0 + 1];
                            split_h2(fmaxf(cc[nt][0] + bb0, 0.0f),
                                     fmaxf(cc[nt][1] + bb1, 0.0f),
                                     aH[kt][ai], aL[kt][ai]);
                            split_h2(fmaxf(cc[nt][2] + bb0, 0.0f),
                                     fmaxf(cc[nt][3] + bb1, 0.0f),
                                     aH[kt][ai + 1], aL[kt][ai + 1]);
                        }
                    } else {
#pragma unroll
                        for (int nt = 0; nt < 4; nt++) {
                            const int c0 = 8 * nt + 2 * q;
                            const float bb0 = bsd[d * WD + c0];
                            const float bb1 = bsd[d * WD + c0 + 1];
                            float v0 = fmaxf(cc[nt][0] + bb0, 0.0f);
                            float v1 = fmaxf(cc[nt][1] + bb1, 0.0f);
                            float v2 = fmaxf(cc[nt][2] + bb0, 0.0f);
                            float v3 = fmaxf(cc[nt][3] + bb1, 0.0f);
                            acc2[0] = fmaf(v0, wo[nt * 2 + 0], fmaf(v1, wo[nt * 2 + 1], acc2[0]));
                            acc2[1] = fmaf(v2, wo[nt * 2 + 0], fmaf(v3, wo[nt * 2 + 1], acc2[1]));
                        }
                    }
                }

                // reduce across the 4-lane column group
#pragma unroll
                for (int jj = 0; jj < 2; jj++) {
                    acc2[jj] += __shfl_xor_sync(0xFFFFFFFFu, acc2[jj], 1);
                    acc2[jj] += __shfl_xor_sync(0xFFFFFFFFu, acc2[jj], 2);
                }
                if (q == 0) {
#pragma unroll
                    for (int jj = 0; jj < 2; jj++) {
                        int rowl = R + g + 8 * jj;
                        int pt = myxp[rowl];
                        if (pt >= 0) out[pt] = acc2[jj] + boutv;
                    }
                }
            }
        }
    }

    __syncthreads();
    if (tid == 0) {
        int old = atomicAdd(&g_done, 1);
        if (old == (int)gridDim.x - 1) {
            g_nact = 0;
            float* s = &g_img_sum[0][0];
            for (int t = 0; t < BB * WD; t++) s[t] = 0.0f;
            for (int t = 0; t < BB; t++) g_img_cnt[t] = 0.0f;
            __threadfence();
            g_done = 0;
        }
    }
}

// ---------------------------------------------------------------------------
extern "C" void kernel_launch(void* const* d_in, const int* in_sizes, int n_in,
                              void* d_out, int out_size)
{
    const float* Imodel   = (const float*)d_in[0];
    const float* Iobs     = (const float*)d_in[1];
    const float* metadata = (const float*)d_in[2];
    const void*  mask     = d_in[3];
    const float* W_img_in = (const float*)d_in[5];
    const float* b_img_in = (const float*)d_in[6];
    const float* W_img    = (const float*)d_in[7];
    const float* b_img    = (const float*)d_in[8];
    const float* W_lin_in = (const float*)d_in[9];
    const float* b_lin_in = (const float*)d_in[10];
    const float* W_mlp    = (const float*)d_in[11];
    const float* b_mlp    = (const float*)d_in[12];
    const float* W_out    = (const float*)d_in[13];
    const float* b_out    = (const float*)d_in[14];
    float* out = (float*)d_out;

    static int smem_set = 0;
    if (!smem_set) {
        cudaFuncSetAttribute(k_main, cudaFuncAttributeMaxDynamicSharedMemorySize,
                             SMEM_BYTES);
        smem_set = 1;
    }

    k_front<<<IMGB + NCOMPB, 256>>>(mask, Imodel, Iobs, metadata,
                                    W_img_in, b_img_in, W_img, b_img, out);
    k_main<<<NMAINB, MT_TPB, SMEM_BYTES>>>(metadata, W_lin_in, b_lin_in,
                                           W_mlp, b_mlp, W_out, b_out, out);
}